// round 1
// baseline (speedup 1.0000x reference)
#include <cuda_runtime.h>
#include <math.h>

// Problem constants (fixed by reference setup_inputs)
#define BN   4
#define NG   16
#define NP   64
#define SZ   32
#define HH   640
#define WW   640
#define NPIX (SZ*SZ)          // 1024
#define NBOX (NG+NP)          // 80
#define NPAIR (BN*NG*NP)      // 4096
#define C1V  6.5025f          // (0.01*255)^2
#define C2V  58.5225f         // (0.03*255)^2
#define THRESH 0.3f

// Scratch (device globals — no runtime allocation allowed)
__device__ float d_gcrop[BN*NG*3*NPIX];
__device__ float d_pcrop[BN*NP*3*NPIX];
__device__ float d_mug  [BN*NG*3*NPIX];
__device__ float d_sigg [BN*NG*3*NPIX];
__device__ float d_mup  [BN*NP*3*NPIX];
__device__ float d_sigp [BN*NP*3*NPIX];
__device__ float d_pair_ssim[NPAIR];
__device__ float d_pair_l1  [NPAIR];
__device__ float d_pair_w   [NPAIR];

__device__ __forceinline__ void make_gauss(float* gk, int tid) {
    if (tid == 0) {
        float tmp[11]; float s = 0.f;
        #pragma unroll
        for (int i = 0; i < 11; i++) {
            float x = (float)i - 5.0f;
            tmp[i] = expf(-x*x / (2.0f * 1.5f * 1.5f));
            s += tmp[i];
        }
        #pragma unroll
        for (int i = 0; i < 11; i++) gk[i] = tmp[i] / s;
    }
}

// ---------------------------------------------------------------------------
// Kernel 1: one block per (batch, box). Bilinear crop -> shared,
// then separable 11x11 Gaussian conv for mu and E[x^2] -> sig.
// ---------------------------------------------------------------------------
__global__ __launch_bounds__(256)
void crop_moments_kernel(const float* __restrict__ imgs,
                         const float* __restrict__ gt,
                         const float* __restrict__ pr)
{
    const int blk = blockIdx.x;          // 0 .. BN*NBOX-1
    const int b   = blk / NBOX;
    const int k   = blk % NBOX;
    const bool isGT = (k < NG);
    const int  bi   = isGT ? (b*NG + k) : (b*NP + (k - NG));

    const float* box      = isGT ? (gt + (b*NG + k)*4) : (pr + (b*NP + (k-NG))*4);
    float* crop_out = isGT ? (d_gcrop + bi*3*NPIX) : (d_pcrop + bi*3*NPIX);
    float* mu_out   = isGT ? (d_mug   + bi*3*NPIX) : (d_mup   + bi*3*NPIX);
    float* sig_out  = isGT ? (d_sigg  + bi*3*NPIX) : (d_sigp  + bi*3*NPIX);

    __shared__ float gk[11];
    __shared__ int   ix0s[SZ], ix1s[SZ], iy0s[SZ], iy1s[SZ];
    __shared__ float fxs[SZ],  fys[SZ];
    __shared__ float crop[3*NPIX];
    __shared__ float t1[NPIX], t2[NPIX];

    const int tid = threadIdx.x;
    make_gauss(gk, tid);

    if (tid < 64) {
        const float cx = box[0], cy = box[1], w = box[2], h = box[3];
        if (tid < 32) {
            float x0 = fminf(fmaxf(floorf(cx - w*0.5f), 0.f), (float)WW - 1.f);
            float x1 = fminf(fmaxf(floorf(cx + w*0.5f), 0.f), (float)WW);
            float wp = fmaxf(x1 - x0, 1.f);
            float dd = (float)tid + 0.5f;
            float sx = x0 + fminf(fmaxf(dd*wp/(float)SZ - 0.5f, 0.f), wp - 1.f);
            float fl = floorf(sx);
            fxs[tid]  = sx - fl;
            int i0    = (int)fl;
            ix0s[tid] = i0;
            ix1s[tid] = min(i0 + 1, (int)(x0 + wp - 1.f));
        } else {
            int t = tid - 32;
            float y0 = fminf(fmaxf(floorf(cy - h*0.5f), 0.f), (float)HH - 1.f);
            float y1 = fminf(fmaxf(floorf(cy + h*0.5f), 0.f), (float)HH);
            float hp = fmaxf(y1 - y0, 1.f);
            float dd = (float)t + 0.5f;
            float sy = y0 + fminf(fmaxf(dd*hp/(float)SZ - 0.5f, 0.f), hp - 1.f);
            float fl = floorf(sy);
            fys[t]  = sy - fl;
            int i0  = (int)fl;
            iy0s[t] = i0;
            iy1s[t] = min(i0 + 1, (int)(y0 + hp - 1.f));
        }
    }
    __syncthreads();

    const float* img = imgs + (size_t)b*3*HH*WW;
    #pragma unroll
    for (int rep = 0; rep < 12; rep++) {         // 3072 / 256
        int p  = tid + rep*256;
        int c  = p / NPIX;
        int q  = p % NPIX;
        int yy = q / SZ;
        int xx = q % SZ;
        const float* ic = img + (size_t)c*HH*WW;
        int i0 = ix0s[xx], i1 = ix1s[xx], j0 = iy0s[yy], j1 = iy1s[yy];
        float fx = fxs[xx], fy = fys[yy];
        float v = ic[j0*WW + i0] * (1.f - fy) * (1.f - fx)
                + ic[j0*WW + i1] * (1.f - fy) * fx
                + ic[j1*WW + i0] * fy * (1.f - fx)
                + ic[j1*WW + i1] * fy * fx;
        crop[p]     = v;
        crop_out[p] = v;
    }
    __syncthreads();

    for (int c = 0; c < 3; c++) {
        const float* cc = crop + c*NPIX;
        // horizontal pass: conv(x) -> t1, conv(x^2) -> t2
        #pragma unroll
        for (int rep = 0; rep < 4; rep++) {      // 1024 / 256
            int p  = tid + rep*256;
            int yy = p / SZ, xx = p % SZ;
            float a = 0.f, bb = 0.f;
            #pragma unroll
            for (int t = 0; t < 11; t++) {
                int x = xx + t - 5;
                if (x >= 0 && x < SZ) {
                    float v = cc[yy*SZ + x];
                    a  += gk[t] * v;
                    bb += gk[t] * v * v;
                }
            }
            t1[p] = a; t2[p] = bb;
        }
        __syncthreads();
        // vertical pass
        #pragma unroll
        for (int rep = 0; rep < 4; rep++) {
            int p  = tid + rep*256;
            int yy = p / SZ, xx = p % SZ;
            float a = 0.f, bb = 0.f;
            #pragma unroll
            for (int t = 0; t < 11; t++) {
                int y = yy + t - 5;
                if (y >= 0 && y < SZ) {
                    a  += gk[t] * t1[y*SZ + xx];
                    bb += gk[t] * t2[y*SZ + xx];
                }
            }
            mu_out [c*NPIX + p] = a;
            sig_out[c*NPIX + p] = bb - a*a;
        }
        __syncthreads();
    }
}

// ---------------------------------------------------------------------------
// Kernel 2: one block per (b, gt_i, pred_j) pair. Early-out on invalid.
// Valid: per channel, separable conv of g*p in shared, fused SSIM + L1.
// ---------------------------------------------------------------------------
__global__ __launch_bounds__(256)
void pair_kernel(const float* __restrict__ gt, const float* __restrict__ pr)
{
    const int blk = blockIdx.x;                  // b*NG*NP + i*NP + j
    const int b = blk / (NG*NP);
    const int r = blk % (NG*NP);
    const int i = r / NP;
    const int j = r % NP;
    const int tid = threadIdx.x;

    const float* gb = gt + (b*NG + i)*4;
    const float* pb = pr + (b*NP + j)*4;
    float gx = gb[0], gy = gb[1], gw = gb[2], gh = gb[3];
    float px = pb[0], py = pb[1], pw = pb[2], ph = pb[3];

    float tlx = fmaxf(gx - gw*0.5f, px - pw*0.5f);
    float tly = fmaxf(gy - gh*0.5f, py - ph*0.5f);
    float brx = fminf(gx + gw*0.5f, px + pw*0.5f);
    float bry = fminf(gy + gh*0.5f, py + ph*0.5f);
    float ag = gw*gh, ap = pw*ph;
    float en = ((tlx < brx) && (tly < bry)) ? 1.f : 0.f;
    float ai = (brx - tlx) * (bry - tly) * en;
    float iou = ai / (ag + ap - ai + 1e-16f);
    bool valid = (iou > THRESH) && (pw > 2.f) && (ph > 2.f);

    if (!valid) {
        if (tid == 0) {
            d_pair_w[blk]    = 0.f;
            d_pair_ssim[blk] = 0.f;
            d_pair_l1[blk]   = 0.f;
        }
        return;
    }

    __shared__ float gk[11];
    __shared__ float gsh[NPIX], psh[NPIX], t1[NPIX];
    __shared__ float red[256];
    make_gauss(gk, tid);

    const float* gbase = d_gcrop + (size_t)(b*NG + i)*3*NPIX;
    const float* pbase = d_pcrop + (size_t)(b*NP + j)*3*NPIX;
    const float* mug   = d_mug   + (size_t)(b*NG + i)*3*NPIX;
    const float* sigg  = d_sigg  + (size_t)(b*NG + i)*3*NPIX;
    const float* mup   = d_mup   + (size_t)(b*NP + j)*3*NPIX;
    const float* sigp  = d_sigp  + (size_t)(b*NP + j)*3*NPIX;

    float acc_ssim = 0.f;
    float acc_l1   = 0.f;

    for (int c = 0; c < 3; c++) {
        __syncthreads();
        #pragma unroll
        for (int rep = 0; rep < 4; rep++) {
            int p = tid + rep*256;
            gsh[p] = gbase[c*NPIX + p];
            psh[p] = pbase[c*NPIX + p];
        }
        __syncthreads();
        // horizontal conv of g*p (on the fly) -> t1
        #pragma unroll
        for (int rep = 0; rep < 4; rep++) {
            int p  = tid + rep*256;
            int yy = p / SZ, xx = p % SZ;
            float a = 0.f;
            #pragma unroll
            for (int t = 0; t < 11; t++) {
                int x = xx + t - 5;
                if (x >= 0 && x < SZ) {
                    int idx = yy*SZ + x;
                    a += gk[t] * gsh[idx] * psh[idx];
                }
            }
            t1[p] = a;
        }
        __syncthreads();
        // vertical conv + SSIM map + L1
        #pragma unroll
        for (int rep = 0; rep < 4; rep++) {
            int p  = tid + rep*256;
            int yy = p / SZ, xx = p % SZ;
            float egp = 0.f;
            #pragma unroll
            for (int t = 0; t < 11; t++) {
                int y = yy + t - 5;
                if (y >= 0 && y < SZ) egp += gk[t] * t1[y*SZ + xx];
            }
            float mg  = mug [c*NPIX + p];
            float mp_ = mup [c*NPIX + p];
            float sg  = sigg[c*NPIX + p];
            float sp  = sigp[c*NPIX + p];
            float sgp = egp - mg*mp_;
            float num = (2.f*mg*mp_ + C1V) * (2.f*sgp + C2V);
            float den = (mg*mg + mp_*mp_ + C1V) * (sg + sp + C2V);
            acc_ssim += num / den;
            acc_l1   += fabsf(gsh[p] - psh[p]) * (1.0f/255.0f);
        }
    }

    // block reduction (ssim then l1)
    red[tid] = acc_ssim;
    __syncthreads();
    #pragma unroll
    for (int s = 128; s > 0; s >>= 1) {
        if (tid < s) red[tid] += red[tid + s];
        __syncthreads();
    }
    float ssim_sum = red[0];
    __syncthreads();
    red[tid] = acc_l1;
    __syncthreads();
    #pragma unroll
    for (int s = 128; s > 0; s >>= 1) {
        if (tid < s) red[tid] += red[tid + s];
        __syncthreads();
    }
    if (tid == 0) {
        d_pair_ssim[blk] = ssim_sum * (1.0f / (3.0f*NPIX));
        d_pair_l1[blk]   = red[0]   * (1.0f / (3.0f*NPIX));
        d_pair_w[blk]    = 1.f;
    }
}

// ---------------------------------------------------------------------------
// Kernel 3: final reduction over 4096 pairs -> scalar loss
// ---------------------------------------------------------------------------
__global__ __launch_bounds__(256)
void finalize_kernel(float* __restrict__ out)
{
    __shared__ float rw[256], rs[256], rl[256];
    const int tid = threadIdx.x;
    float cw = 0.f, cs = 0.f, cl = 0.f;
    for (int p = tid; p < NPAIR; p += 256) {
        cw += d_pair_w[p];
        cs += d_pair_ssim[p];
        cl += d_pair_l1[p];
    }
    rw[tid] = cw; rs[tid] = cs; rl[tid] = cl;
    __syncthreads();
    #pragma unroll
    for (int s = 128; s > 0; s >>= 1) {
        if (tid < s) { rw[tid] += rw[tid+s]; rs[tid] += rs[tid+s]; rl[tid] += rl[tid+s]; }
        __syncthreads();
    }
    if (tid == 0) {
        float cnt   = rw[0];
        float denom = fmaxf(cnt, 1.f);
        float loss  = rl[0] / denom + 1.f - rs[0] / denom;
        out[0] = (cnt > 0.f) ? loss : 0.f;
    }
}

extern "C" void kernel_launch(void* const* d_in, const int* in_sizes, int n_in,
                              void* d_out, int out_size)
{
    const float* imgs = (const float*)d_in[0];   // (4,3,640,640)
    const float* gt   = (const float*)d_in[1];   // (4,16,4)
    const float* pr   = (const float*)d_in[2];   // (4,64,4)
    float* out = (float*)d_out;

    crop_moments_kernel<<<BN*NBOX, 256>>>(imgs, gt, pr);
    pair_kernel<<<NPAIR, 256>>>(gt, pr);
    finalize_kernel<<<1, 256>>>(out);
}

// round 2
// speedup vs baseline: 1.5099x; 1.5099x over previous
#include <cuda_runtime.h>
#include <math.h>

#define BN   4
#define NG   16
#define NP   64
#define SZ   32
#define HH   640
#define WW   640
#define NPIX (SZ*SZ)          // 1024
#define NBOX (NG+NP)          // 80
#define NPAIR (BN*NG*NP)      // 4096
#define C1V  6.5025f
#define C2V  58.5225f
#define THRESH 0.3f
#define PADW 42               // 32 + 2*5

// Normalized 11-tap Gaussian (sigma=1.5), matches fp32 reference to ~1e-6
__constant__ float GK[11] = {
    0.00102838f, 0.00759870f, 0.03600077f, 0.10936100f, 0.21300570f,
    0.26601172f,
    0.21300570f, 0.10936100f, 0.03600077f, 0.00759870f, 0.00102838f
};

// Scratch (device globals — no runtime allocation allowed)
__device__ float d_gcrop[BN*NG*3*NPIX];
__device__ float d_pcrop[BN*NP*3*NPIX];
__device__ float d_mug  [BN*NG*3*NPIX];
__device__ float d_sigg [BN*NG*3*NPIX];
__device__ float d_mup  [BN*NP*3*NPIX];
__device__ float d_sigp [BN*NP*3*NPIX];
__device__ int   d_valid_cnt;
__device__ int   d_valid_idx[NPAIR];
__device__ float d_v_ssim[NPAIR*3];
__device__ float d_v_l1  [NPAIR*3];

// ---------------------------------------------------------------------------
// Kernel 1: blocks [0, 960): one per (batch, box, channel) — crop + moments.
//           block 960: pair validity + deterministic compaction.
// ---------------------------------------------------------------------------
__global__ __launch_bounds__(256)
void crop_valid_kernel(const float* __restrict__ imgs,
                       const float* __restrict__ gt,
                       const float* __restrict__ pr)
{
    const int blk = blockIdx.x;
    const int tid = threadIdx.x;

    if (blk == BN*NBOX*3) {
        // ---- validity + compaction (4096 pairs, 16 per thread, in order) ----
        __shared__ int sc[256];
        int flags = 0;          // bitmask of 16 pairs
        int cnt = 0;
        const int base = tid * 16;
        #pragma unroll
        for (int q = 0; q < 16; q++) {
            int pair = base + q;
            int b = pair >> 10, r = pair & 1023, i = r >> 6, j = r & 63;
            const float* gb = gt + (b*NG + i)*4;
            const float* pb = pr + (b*NP + j)*4;
            float gx = gb[0], gy = gb[1], gw = gb[2], gh = gb[3];
            float px = pb[0], py = pb[1], pw = pb[2], ph = pb[3];
            float tlx = fmaxf(gx - gw*0.5f, px - pw*0.5f);
            float tly = fmaxf(gy - gh*0.5f, py - ph*0.5f);
            float brx = fminf(gx + gw*0.5f, px + pw*0.5f);
            float bry = fminf(gy + gh*0.5f, py + ph*0.5f);
            float en = ((tlx < brx) && (tly < bry)) ? 1.f : 0.f;
            float ai = (brx - tlx) * (bry - tly) * en;
            float iou = ai / (gw*gh + pw*ph - ai + 1e-16f);
            bool valid = (iou > THRESH) && (pw > 2.f) && (ph > 2.f);
            if (valid) { flags |= (1 << q); cnt++; }
        }
        sc[tid] = cnt;
        __syncthreads();
        // Hillis-Steele inclusive scan
        for (int d = 1; d < 256; d <<= 1) {
            int v = sc[tid];
            if (tid >= d) v += sc[tid - d];
            __syncthreads();
            sc[tid] = v;
            __syncthreads();
        }
        int off = sc[tid] - cnt;
        #pragma unroll
        for (int q = 0; q < 16; q++) {
            if (flags & (1 << q)) d_valid_idx[off++] = base + q;
        }
        if (tid == 255) d_valid_cnt = sc[255];
        return;
    }

    // ---- crop + moments for one (b, box, channel) ----
    const int b   = blk / (NBOX*3);
    const int rem = blk % (NBOX*3);
    const int k   = rem / 3;
    const int c   = rem % 3;
    const bool isGT = (k < NG);
    const int  bi   = isGT ? (b*NG + k) : (b*NP + (k - NG));

    const float* box = isGT ? (gt + (b*NG + k)*4) : (pr + (b*NP + (k-NG))*4);
    float* crop_out  = (isGT ? d_gcrop : d_pcrop) + (size_t)bi*3*NPIX + c*NPIX;
    float* mu_out    = (isGT ? d_mug   : d_mup  ) + (size_t)bi*3*NPIX + c*NPIX;
    float* sig_out   = (isGT ? d_sigg  : d_sigp ) + (size_t)bi*3*NPIX + c*NPIX;

    __shared__ int   ix0s[SZ], ix1s[SZ], iy0s[SZ], iy1s[SZ];
    __shared__ float fxs[SZ],  fys[SZ];
    __shared__ float csh[SZ*PADW];      // 32 rows x 42 cols (x-padded)
    __shared__ float t1[PADW*SZ];       // 42 rows x 32 cols (y-padded)
    __shared__ float t2[PADW*SZ];

    // zero padded arrays (pads stay zero; interiors overwritten after sync)
    for (int p = tid; p < SZ*PADW; p += 256) { csh[p] = 0.f; }
    for (int p = tid; p < PADW*SZ; p += 256) { t1[p] = 0.f; t2[p] = 0.f; }

    if (tid < 64) {
        const float cx = box[0], cy = box[1], w = box[2], h = box[3];
        if (tid < 32) {
            float x0 = fminf(fmaxf(floorf(cx - w*0.5f), 0.f), (float)WW - 1.f);
            float x1 = fminf(fmaxf(floorf(cx + w*0.5f), 0.f), (float)WW);
            float wp = fmaxf(x1 - x0, 1.f);
            float dd = (float)tid + 0.5f;
            float sx = x0 + fminf(fmaxf(dd*wp/(float)SZ - 0.5f, 0.f), wp - 1.f);
            float fl = floorf(sx);
            fxs[tid]  = sx - fl;
            int i0    = (int)fl;
            ix0s[tid] = i0;
            ix1s[tid] = min(i0 + 1, (int)(x0 + wp - 1.f));
        } else {
            int t = tid - 32;
            float y0 = fminf(fmaxf(floorf(cy - h*0.5f), 0.f), (float)HH - 1.f);
            float y1 = fminf(fmaxf(floorf(cy + h*0.5f), 0.f), (float)HH);
            float hp = fmaxf(y1 - y0, 1.f);
            float dd = (float)t + 0.5f;
            float sy = y0 + fminf(fmaxf(dd*hp/(float)SZ - 0.5f, 0.f), hp - 1.f);
            float fl = floorf(sy);
            fys[t]  = sy - fl;
            int i0  = (int)fl;
            iy0s[t] = i0;
            iy1s[t] = min(i0 + 1, (int)(y0 + hp - 1.f));
        }
    }
    __syncthreads();

    const float* ic = imgs + ((size_t)b*3 + c)*HH*WW;
    #pragma unroll
    for (int rep = 0; rep < 4; rep++) {
        int p  = tid + rep*256;
        int yy = p >> 5, xx = p & 31;
        int i0 = ix0s[xx], i1 = ix1s[xx], j0 = iy0s[yy], j1 = iy1s[yy];
        float fx = fxs[xx], fy = fys[yy];
        float v = ic[j0*WW + i0] * (1.f - fy) * (1.f - fx)
                + ic[j0*WW + i1] * (1.f - fy) * fx
                + ic[j1*WW + i0] * fy * (1.f - fx)
                + ic[j1*WW + i1] * fy * fx;
        csh[yy*PADW + xx + 5] = v;
        crop_out[p] = v;
    }
    __syncthreads();

    // horizontal pass (branch-free via zero padding)
    #pragma unroll
    for (int rep = 0; rep < 4; rep++) {
        int p  = tid + rep*256;
        int yy = p >> 5, xx = p & 31;
        float a = 0.f, bb = 0.f;
        const float* row = csh + yy*PADW + xx;
        #pragma unroll
        for (int t = 0; t < 11; t++) {
            float v = row[t];
            a  = fmaf(GK[t], v,   a);
            bb = fmaf(GK[t], v*v, bb);
        }
        t1[(yy+5)*SZ + xx] = a;
        t2[(yy+5)*SZ + xx] = bb;
    }
    __syncthreads();

    // vertical pass
    #pragma unroll
    for (int rep = 0; rep < 4; rep++) {
        int p  = tid + rep*256;
        int yy = p >> 5, xx = p & 31;
        float a = 0.f, bb = 0.f;
        #pragma unroll
        for (int t = 0; t < 11; t++) {
            a  = fmaf(GK[t], t1[(yy+t)*SZ + xx], a);
            bb = fmaf(GK[t], t2[(yy+t)*SZ + xx], bb);
        }
        mu_out [p] = a;
        sig_out[p] = bb - a*a;
    }
}

// ---------------------------------------------------------------------------
// Kernel 2: one block per (valid pair, channel). Blocks beyond 3*count exit
// after a single load.
// ---------------------------------------------------------------------------
__global__ __launch_bounds__(256)
void pair_kernel()
{
    const int v = blockIdx.x / 3;
    if (v >= d_valid_cnt) return;
    const int c = blockIdx.x % 3;
    const int pair = d_valid_idx[v];
    const int b = pair >> 10, r = pair & 1023, i = r >> 6, j = r & 63;
    const int tid = threadIdx.x;

    __shared__ float gsh[SZ*PADW], psh[SZ*PADW];   // x-padded
    __shared__ float t1[PADW*SZ];                  // y-padded
    __shared__ float ws[8], wl[8];

    for (int p = tid; p < SZ*PADW; p += 256) { gsh[p] = 0.f; psh[p] = 0.f; }
    for (int p = tid; p < PADW*SZ; p += 256) { t1[p] = 0.f; }
    __syncthreads();

    const float* gbase = d_gcrop + ((size_t)(b*NG + i)*3 + c)*NPIX;
    const float* pbase = d_pcrop + ((size_t)(b*NP + j)*3 + c)*NPIX;
    const float* mug   = d_mug   + ((size_t)(b*NG + i)*3 + c)*NPIX;
    const float* sigg  = d_sigg  + ((size_t)(b*NG + i)*3 + c)*NPIX;
    const float* mup   = d_mup   + ((size_t)(b*NP + j)*3 + c)*NPIX;
    const float* sigp  = d_sigp  + ((size_t)(b*NP + j)*3 + c)*NPIX;

    #pragma unroll
    for (int rep = 0; rep < 4; rep++) {
        int p  = tid + rep*256;
        int yy = p >> 5, xx = p & 31;
        gsh[yy*PADW + xx + 5] = gbase[p];
        psh[yy*PADW + xx + 5] = pbase[p];
    }
    __syncthreads();

    // horizontal conv of g*p
    #pragma unroll
    for (int rep = 0; rep < 4; rep++) {
        int p  = tid + rep*256;
        int yy = p >> 5, xx = p & 31;
        const float* gr = gsh + yy*PADW + xx;
        const float* pr_ = psh + yy*PADW + xx;
        float a = 0.f;
        #pragma unroll
        for (int t = 0; t < 11; t++) a = fmaf(GK[t], gr[t]*pr_[t], a);
        t1[(yy+5)*SZ + xx] = a;
    }
    __syncthreads();

    // vertical conv + SSIM + L1
    float acc_ssim = 0.f, acc_l1 = 0.f;
    #pragma unroll
    for (int rep = 0; rep < 4; rep++) {
        int p  = tid + rep*256;
        int yy = p >> 5, xx = p & 31;
        float egp = 0.f;
        #pragma unroll
        for (int t = 0; t < 11; t++) egp = fmaf(GK[t], t1[(yy+t)*SZ + xx], egp);
        float mg  = mug [p];
        float mp_ = mup [p];
        float sg  = sigg[p];
        float sp  = sigp[p];
        float sgp = egp - mg*mp_;
        float num = (2.f*mg*mp_ + C1V) * (2.f*sgp + C2V);
        float den = (mg*mg + mp_*mp_ + C1V) * (sg + sp + C2V);
        acc_ssim += num / den;
        float gv = gsh[yy*PADW + xx + 5];
        float pv = psh[yy*PADW + xx + 5];
        acc_l1  += fabsf(gv - pv) * (1.0f/255.0f);
    }

    // warp-shuffle reduction
    #pragma unroll
    for (int o = 16; o > 0; o >>= 1) {
        acc_ssim += __shfl_down_sync(0xffffffffu, acc_ssim, o);
        acc_l1   += __shfl_down_sync(0xffffffffu, acc_l1,   o);
    }
    if ((tid & 31) == 0) { ws[tid >> 5] = acc_ssim; wl[tid >> 5] = acc_l1; }
    __syncthreads();
    if (tid == 0) {
        float s = 0.f, l = 0.f;
        #pragma unroll
        for (int w = 0; w < 8; w++) { s += ws[w]; l += wl[w]; }
        d_v_ssim[v*3 + c] = s;
        d_v_l1  [v*3 + c] = l;
    }
}

// ---------------------------------------------------------------------------
// Kernel 3: final reduction over valid (pair, channel) entries -> loss
// ---------------------------------------------------------------------------
__global__ __launch_bounds__(256)
void finalize_kernel(float* __restrict__ out)
{
    __shared__ float rs[256], rl[256];
    const int tid = threadIdx.x;
    const int n = d_valid_cnt * 3;
    float cs = 0.f, cl = 0.f;
    for (int p = tid; p < n; p += 256) { cs += d_v_ssim[p]; cl += d_v_l1[p]; }
    rs[tid] = cs; rl[tid] = cl;
    __syncthreads();
    #pragma unroll
    for (int s = 128; s > 0; s >>= 1) {
        if (tid < s) { rs[tid] += rs[tid+s]; rl[tid] += rl[tid+s]; }
        __syncthreads();
    }
    if (tid == 0) {
        float cnt   = (float)d_valid_cnt;
        float denom = fmaxf(cnt, 1.f) * 3.0f * (float)NPIX;
        float loss  = rl[0] / denom + 1.f - rs[0] / denom;
        out[0] = (cnt > 0.f) ? loss : 0.f;
    }
}

extern "C" void kernel_launch(void* const* d_in, const int* in_sizes, int n_in,
                              void* d_out, int out_size)
{
    const float* imgs = (const float*)d_in[0];   // (4,3,640,640)
    const float* gt   = (const float*)d_in[1];   // (4,16,4)
    const float* pr   = (const float*)d_in[2];   // (4,64,4)
    float* out = (float*)d_out;

    crop_valid_kernel<<<BN*NBOX*3 + 1, 256>>>(imgs, gt, pr);
    pair_kernel<<<NPAIR*3, 256>>>();
    finalize_kernel<<<1, 256>>>(out);
}

// round 3
// speedup vs baseline: 1.6238x; 1.0755x over previous
#include <cuda_runtime.h>
#include <math.h>

#define BN   4
#define NG   16
#define NP   64
#define SZ   32
#define HH   640
#define WW   640
#define NPIX (SZ*SZ)          // 1024
#define NBOX (NG+NP)          // 80
#define NPAIR (BN*NG*NP)      // 4096
#define C1V  6.5025f
#define C2V  58.5225f
#define THRESH 0.3f
#define PX   49               // x-padded pitch (8 left pad, interior at +8), odd -> conflict-free
#define PY   45               // y-padded pitch (5 top pad), odd -> conflict-free
#define PAIR_GRID 1184        // 148 SMs * 8

// Normalized 11-tap Gaussian (sigma=1.5)
__constant__ float GK[11] = {
    0.00102838f, 0.00759870f, 0.03600077f, 0.10936100f, 0.21300570f,
    0.26601172f,
    0.21300570f, 0.10936100f, 0.03600077f, 0.00759870f, 0.00102838f
};

// Scratch (device globals)
__device__ __align__(128) float d_gcrop[BN*NG*3*NPIX];
__device__ __align__(128) float d_pcrop[BN*NP*3*NPIX];
__device__ __align__(128) float d_mug  [BN*NG*3*NPIX];
__device__ __align__(128) float d_sigg [BN*NG*3*NPIX];
__device__ __align__(128) float d_mup  [BN*NP*3*NPIX];
__device__ __align__(128) float d_sigp [BN*NP*3*NPIX];
__device__ int   d_valid_cnt;
__device__ unsigned int d_done;
__device__ int   d_valid_idx[NPAIR];
__device__ float d_v_ssim[NPAIR*3];
__device__ float d_v_l1  [NPAIR*3];

// ---------------------------------------------------------------------------
// Kernel A: blocks [0,960): crop + moments per (batch, box, channel).
//           block 960: pair validity + compaction + counter reset.
// ---------------------------------------------------------------------------
__global__ __launch_bounds__(256)
void crop_valid_kernel(const float* __restrict__ imgs,
                       const float* __restrict__ gt,
                       const float* __restrict__ pr)
{
    const int blk = blockIdx.x;
    const int tid = threadIdx.x;

    if (blk == BN*NBOX*3) {
        __shared__ int sc[256];
        int flags = 0, cnt = 0;
        const int base = tid * 16;
        #pragma unroll
        for (int q = 0; q < 16; q++) {
            int pair = base + q;
            int b = pair >> 10, r = pair & 1023, i = r >> 6, j = r & 63;
            const float* gb = gt + (b*NG + i)*4;
            const float* pb = pr + (b*NP + j)*4;
            float gx = gb[0], gy = gb[1], gw = gb[2], gh = gb[3];
            float px = pb[0], py = pb[1], pw = pb[2], ph = pb[3];
            float tlx = fmaxf(gx - gw*0.5f, px - pw*0.5f);
            float tly = fmaxf(gy - gh*0.5f, py - ph*0.5f);
            float brx = fminf(gx + gw*0.5f, px + pw*0.5f);
            float bry = fminf(gy + gh*0.5f, py + ph*0.5f);
            float en = ((tlx < brx) && (tly < bry)) ? 1.f : 0.f;
            float ai = (brx - tlx) * (bry - tly) * en;
            float iou = ai / (gw*gh + pw*ph - ai + 1e-16f);
            bool valid = (iou > THRESH) && (pw > 2.f) && (ph > 2.f);
            if (valid) { flags |= (1 << q); cnt++; }
        }
        sc[tid] = cnt;
        __syncthreads();
        for (int d = 1; d < 256; d <<= 1) {
            int v = sc[tid];
            if (tid >= d) v += sc[tid - d];
            __syncthreads();
            sc[tid] = v;
            __syncthreads();
        }
        int off = sc[tid] - cnt;
        #pragma unroll
        for (int q = 0; q < 16; q++)
            if (flags & (1 << q)) d_valid_idx[off++] = base + q;
        if (tid == 255) d_valid_cnt = sc[255];
        if (tid == 0)   d_done = 0u;
        return;
    }

    const int b   = blk / (NBOX*3);
    const int rem = blk % (NBOX*3);
    const int k   = rem / 3;
    const int c   = rem % 3;
    const bool isGT = (k < NG);
    const int  bi   = isGT ? (b*NG + k) : (b*NP + (k - NG));

    const float* box = isGT ? (gt + (b*NG + k)*4) : (pr + (b*NP + (k-NG))*4);
    float* crop_out  = (isGT ? d_gcrop : d_pcrop) + (size_t)bi*3*NPIX + c*NPIX;
    float* mu_out    = (isGT ? d_mug   : d_mup  ) + (size_t)bi*3*NPIX + c*NPIX;
    float* sig_out   = (isGT ? d_sigg  : d_sigp ) + (size_t)bi*3*NPIX + c*NPIX;

    __shared__ int   ix0s[SZ], ix1s[SZ], iy0s[SZ], iy1s[SZ];
    __shared__ float fxs[SZ],  fys[SZ];
    __shared__ __align__(16) float csh[SZ*PX];   // x-padded crop
    __shared__ __align__(16) float t1 [SZ*PY];   // col-major, y-padded (conv x)
    __shared__ __align__(16) float t2 [SZ*PY];   // (conv x^2)

    // zero (pads matter; interiors overwritten)
    for (int p = tid; p < SZ*PX; p += 256) csh[p] = 0.f;
    for (int p = tid; p < SZ*PY; p += 256) { t1[p] = 0.f; t2[p] = 0.f; }

    if (tid < 64) {
        const float cx = box[0], cy = box[1], w = box[2], h = box[3];
        if (tid < 32) {
            float x0 = fminf(fmaxf(floorf(cx - w*0.5f), 0.f), (float)WW - 1.f);
            float x1 = fminf(fmaxf(floorf(cx + w*0.5f), 0.f), (float)WW);
            float wp = fmaxf(x1 - x0, 1.f);
            float dd = (float)tid + 0.5f;
            float sx = x0 + fminf(fmaxf(dd*wp/(float)SZ - 0.5f, 0.f), wp - 1.f);
            float fl = floorf(sx);
            fxs[tid]  = sx - fl;
            int i0    = (int)fl;
            ix0s[tid] = i0;
            ix1s[tid] = min(i0 + 1, (int)(x0 + wp - 1.f));
        } else {
            int t = tid - 32;
            float y0 = fminf(fmaxf(floorf(cy - h*0.5f), 0.f), (float)HH - 1.f);
            float y1 = fminf(fmaxf(floorf(cy + h*0.5f), 0.f), (float)HH);
            float hp = fmaxf(y1 - y0, 1.f);
            float dd = (float)t + 0.5f;
            float sy = y0 + fminf(fmaxf(dd*hp/(float)SZ - 0.5f, 0.f), hp - 1.f);
            float fl = floorf(sy);
            fys[t]  = sy - fl;
            int i0  = (int)fl;
            iy0s[t] = i0;
            iy1s[t] = min(i0 + 1, (int)(y0 + hp - 1.f));
        }
    }
    __syncthreads();

    // ---- bilinear gather: thread -> (row = tid>>3, 4 px at xq = (tid&7)*4)
    {
        const int row = tid >> 3;
        const int xq  = (tid & 7) << 2;
        const float* ic = imgs + ((size_t)b*3 + c)*HH*WW;
        const int j0 = iy0s[row], j1 = iy1s[row];
        const float fy = fys[row];
        float4 vout;
        float* vp = (float*)&vout;
        #pragma unroll
        for (int q = 0; q < 4; q++) {
            int xx = xq + q;
            int i0 = ix0s[xx], i1 = ix1s[xx];
            float fx = fxs[xx];
            float v = ic[j0*WW + i0] * (1.f - fy) * (1.f - fx)
                    + ic[j0*WW + i1] * (1.f - fy) * fx
                    + ic[j1*WW + i0] * fy * (1.f - fx)
                    + ic[j1*WW + i1] * fy * fx;
            csh[row*PX + 8 + xx] = v;
            vp[q] = v;
        }
        *(float4*)(crop_out + row*SZ + xq) = vout;
    }
    __syncthreads();

    // ---- horizontal conv: 4 outputs per thread from 14 shared loads
    {
        const int row = tid >> 3;
        const int xq  = (tid & 7) << 2;
        const float* base = csh + row*PX + xq + 3;   // = +8 + xq - 5
        float in[14], sq[14];
        #pragma unroll
        for (int k2 = 0; k2 < 14; k2++) { in[k2] = base[k2]; sq[k2] = in[k2]*in[k2]; }
        #pragma unroll
        for (int q = 0; q < 4; q++) {
            float a = 0.f, bb = 0.f;
            #pragma unroll
            for (int t = 0; t < 11; t++) {
                a  = fmaf(GK[t], in[q+t], a);
                bb = fmaf(GK[t], sq[q+t], bb);
            }
            t1[(xq+q)*PY + row + 5] = a;
            t2[(xq+q)*PY + row + 5] = bb;
        }
    }
    __syncthreads();

    // ---- vertical conv: thread -> (col x = tid&31, 4 rows at yq=(tid>>5)*4)
    {
        const int x  = tid & 31;
        const int yq = (tid >> 5) << 2;
        const float* b1 = t1 + x*PY + yq;
        const float* b2 = t2 + x*PY + yq;
        float u1[14], u2[14];
        #pragma unroll
        for (int k2 = 0; k2 < 14; k2++) { u1[k2] = b1[k2]; u2[k2] = b2[k2]; }
        #pragma unroll
        for (int q = 0; q < 4; q++) {
            float a = 0.f, bb = 0.f;
            #pragma unroll
            for (int t = 0; t < 11; t++) {
                a  = fmaf(GK[t], u1[q+t], a);
                bb = fmaf(GK[t], u2[q+t], bb);
            }
            mu_out [(yq+q)*SZ + x] = a;
            sig_out[(yq+q)*SZ + x] = bb - a*a;
        }
    }
}

// ---------------------------------------------------------------------------
// Kernel B: fixed grid, work-loop over 3*valid_cnt items, fused finalize.
// ---------------------------------------------------------------------------
__global__ __launch_bounds__(256)
void pair_kernel(float* __restrict__ out)
{
    const int tid = threadIdx.x;
    const int nitems = d_valid_cnt * 3;

    __shared__ __align__(16) float gsh[SZ*PX], psh[SZ*PX];
    __shared__ __align__(16) float t1 [SZ*PY];
    __shared__ float ws[8], wl[8];
    __shared__ bool last;

    for (int p = tid; p < SZ*PX; p += 256) { gsh[p] = 0.f; psh[p] = 0.f; }
    for (int p = tid; p < SZ*PY; p += 256) t1[p] = 0.f;
    __syncthreads();

    for (int it = blockIdx.x; it < nitems; it += PAIR_GRID) {
        const int v = it / 3;
        const int c = it - v*3;
        const int pair = d_valid_idx[v];
        const int b = pair >> 10, r = pair & 1023, i = r >> 6, j = r & 63;

        const float* gbase = d_gcrop + ((size_t)(b*NG + i)*3 + c)*NPIX;
        const float* pbase = d_pcrop + ((size_t)(b*NP + j)*3 + c)*NPIX;
        const float* mug   = d_mug   + ((size_t)(b*NG + i)*3 + c)*NPIX;
        const float* sigg  = d_sigg  + ((size_t)(b*NG + i)*3 + c)*NPIX;
        const float* mup   = d_mup   + ((size_t)(b*NP + j)*3 + c)*NPIX;
        const float* sigp  = d_sigp  + ((size_t)(b*NP + j)*3 + c)*NPIX;

        // load tiles (float4)
        {
            const int row = tid >> 3;
            const int xq  = (tid & 7) << 2;
            float4 g4 = *(const float4*)(gbase + row*SZ + xq);
            float4 p4 = *(const float4*)(pbase + row*SZ + xq);
            float* gp = (float*)&g4;
            float* pp = (float*)&p4;
            #pragma unroll
            for (int q = 0; q < 4; q++) {
                gsh[row*PX + 8 + xq + q] = gp[q];
                psh[row*PX + 8 + xq + q] = pp[q];
            }
        }
        __syncthreads();

        // horizontal conv of g*p
        {
            const int row = tid >> 3;
            const int xq  = (tid & 7) << 2;
            const float* gb2 = gsh + row*PX + xq + 3;
            const float* pb2 = psh + row*PX + xq + 3;
            float in[14];
            #pragma unroll
            for (int k2 = 0; k2 < 14; k2++) in[k2] = gb2[k2] * pb2[k2];
            #pragma unroll
            for (int q = 0; q < 4; q++) {
                float a = 0.f;
                #pragma unroll
                for (int t = 0; t < 11; t++) a = fmaf(GK[t], in[q+t], a);
                t1[(xq+q)*PY + row + 5] = a;
            }
        }
        __syncthreads();

        // vertical conv + SSIM + L1
        float acc_ssim = 0.f, acc_l1 = 0.f;
        {
            const int x  = tid & 31;
            const int yq = (tid >> 5) << 2;
            const float* b1 = t1 + x*PY + yq;
            float u[14];
            #pragma unroll
            for (int k2 = 0; k2 < 14; k2++) u[k2] = b1[k2];
            #pragma unroll
            for (int q = 0; q < 4; q++) {
                float egp = 0.f;
                #pragma unroll
                for (int t = 0; t < 11; t++) egp = fmaf(GK[t], u[q+t], egp);
                const int p = (yq+q)*SZ + x;
                float mg  = mug [p];
                float mp_ = mup [p];
                float sg  = sigg[p];
                float sp  = sigp[p];
                float sgp = egp - mg*mp_;
                float num = (2.f*mg*mp_ + C1V) * (2.f*sgp + C2V);
                float den = (mg*mg + mp_*mp_ + C1V) * (sg + sp + C2V);
                acc_ssim += num / den;
                float gv = gsh[(yq+q)*PX + 8 + x];
                float pv = psh[(yq+q)*PX + 8 + x];
                acc_l1  += fabsf(gv - pv) * (1.0f/255.0f);
            }
        }

        #pragma unroll
        for (int o = 16; o > 0; o >>= 1) {
            acc_ssim += __shfl_down_sync(0xffffffffu, acc_ssim, o);
            acc_l1   += __shfl_down_sync(0xffffffffu, acc_l1,   o);
        }
        if ((tid & 31) == 0) { ws[tid >> 5] = acc_ssim; wl[tid >> 5] = acc_l1; }
        __syncthreads();
        if (tid == 0) {
            float s = 0.f, l = 0.f;
            #pragma unroll
            for (int w = 0; w < 8; w++) { s += ws[w]; l += wl[w]; }
            d_v_ssim[it] = s;
            d_v_l1  [it] = l;
        }
        __syncthreads();   // protect smem reuse next iteration
    }

    // ---- fused finalize: last block to arrive reduces everything
    if (tid == 0) {
        __threadfence();
        unsigned int t = atomicAdd(&d_done, 1u);
        last = (t == PAIR_GRID - 1u);
    }
    __syncthreads();
    if (!last) return;
    __threadfence();

    __shared__ float rs[256], rl[256];
    float cs = 0.f, cl = 0.f;
    for (int p = tid; p < nitems; p += 256) { cs += d_v_ssim[p]; cl += d_v_l1[p]; }
    rs[tid] = cs; rl[tid] = cl;
    __syncthreads();
    #pragma unroll
    for (int s = 128; s > 0; s >>= 1) {
        if (tid < s) { rs[tid] += rs[tid+s]; rl[tid] += rl[tid+s]; }
        __syncthreads();
    }
    if (tid == 0) {
        float cnt   = (float)d_valid_cnt;
        float denom = fmaxf(cnt, 1.f) * 3.0f * (float)NPIX;
        float loss  = rl[0] / denom + 1.f - rs[0] / denom;
        out[0] = (cnt > 0.f) ? loss : 0.f;
    }
}

extern "C" void kernel_launch(void* const* d_in, const int* in_sizes, int n_in,
                              void* d_out, int out_size)
{
    const float* imgs = (const float*)d_in[0];   // (4,3,640,640)
    const float* gt   = (const float*)d_in[1];   // (4,16,4)
    const float* pr   = (const float*)d_in[2];   // (4,64,4)
    float* out = (float*)d_out;

    crop_valid_kernel<<<BN*NBOX*3 + 1, 256>>>(imgs, gt, pr);
    pair_kernel<<<PAIR_GRID, 256>>>(out);
}